// round 6
// baseline (speedup 1.0000x reference)
#include <cuda_runtime.h>

// FWHT (11 stages, N=2048) + sign flip on last quarter, batch 16384.
// TWO warps per row, 32 fp32/thread. Per half-row (fixed bit10):
//   bits 0,1  -> register-local (inside float4)
//   bits 2..6 -> warp shuffles (5 stages x 32 values)
//   bits 7,8,9-> register-local across r (3 bits)
//   bit 10    -> one shared-memory half-exchange between the warp pair
// Scale (1/sqrt2)^11 = 2^-5.5 folded into store; sign<0 iff i>=1536 <=> (bit10 & bit9).

__global__ void __launch_bounds__(256)
fwht_sign_kernel2(const float* __restrict__ in, float* __restrict__ out, int rows) {
    __shared__ float sbuf[4][2048];          // 4 rows per 256-thread block, 32 KB

    const int warp     = threadIdx.x >> 5;   // 0..7
    const int lane     = threadIdx.x & 31;
    const int rowLocal = warp >> 1;          // 0..3
    const int half     = warp & 1;           // bit 10 of the global index
    const int row      = blockIdx.x * 4 + rowLocal;
    const bool active  = (row < rows);

    float v[32];

    if (active) {
        const float4* __restrict__ src =
            reinterpret_cast<const float4*>(in) + (size_t)row * 512 + half * 256;

        // Coalesced load: 8 x float4, each instr covers 512 contiguous bytes.
        #pragma unroll
        for (int r = 0; r < 8; r++) {
            float4 f = src[r * 32 + lane];
            v[4*r+0] = f.x; v[4*r+1] = f.y; v[4*r+2] = f.z; v[4*r+3] = f.w;
        }

        // Stages bit0, bit1 (inside the float4).
        #pragma unroll
        for (int r = 0; r < 8; r++) {
            float a0 = v[4*r+0], a1 = v[4*r+1], a2 = v[4*r+2], a3 = v[4*r+3];
            float b0 = a0 + a1, b1 = a0 - a1, b2 = a2 + a3, b3 = a2 - a3;
            v[4*r+0] = b0 + b2;
            v[4*r+1] = b1 + b3;
            v[4*r+2] = b0 - b2;
            v[4*r+3] = b1 - b3;
        }

        // Stages bits 2..6 (lane bits) via warp shuffles.
        #pragma unroll
        for (int h = 1; h <= 16; h <<= 1) {
            const bool upper = (lane & h) != 0;
            #pragma unroll
            for (int k = 0; k < 32; k++) {
                float o = __shfl_xor_sync(0xffffffffu, v[k], h);
                v[k] = upper ? (o - v[k]) : (v[k] + o);
            }
        }

        // Stages bits 7,8,9 (r bits), register-local.
        #pragma unroll
        for (int rh = 1; rh <= 4; rh <<= 1) {
            #pragma unroll
            for (int r = 0; r < 8; r++) {
                if (r & rh) continue;
                #pragma unroll
                for (int c = 0; c < 4; c++) {
                    float a = v[4*r+c];
                    float b = v[4*(r|rh)+c];
                    v[4*r+c]      = a + b;
                    v[4*(r|rh)+c] = a - b;
                }
            }
        }

        // Publish own half to shared memory (conflict-free STS.128).
        float4* sb = reinterpret_cast<float4*>(sbuf[rowLocal]);
        #pragma unroll
        for (int r = 0; r < 8; r++) {
            float4 f;
            f.x = v[4*r+0]; f.y = v[4*r+1]; f.z = v[4*r+2]; f.w = v[4*r+3];
            sb[half * 256 + r * 32 + lane] = f;
        }
    }

    __syncthreads();

    if (active) {
        const float4* sb = reinterpret_cast<const float4*>(sbuf[rowLocal]);
        float4* __restrict__ dst =
            reinterpret_cast<float4*>(out) + (size_t)row * 512 + half * 256;

        const float S = 0.022097086912079612f;   // (1/sqrt(2))^11

        // Stage bit10 from partner half + scale/sign + coalesced store.
        #pragma unroll
        for (int r = 0; r < 8; r++) {
            float4 p = sb[(half ^ 1) * 256 + r * 32 + lane];
            float4 o;
            if (half == 0) {           // out = a + b
                o.x = v[4*r+0] + p.x; o.y = v[4*r+1] + p.y;
                o.z = v[4*r+2] + p.z; o.w = v[4*r+3] + p.w;
            } else {                   // out = a - b  (a = partner's low half)
                o.x = p.x - v[4*r+0]; o.y = p.y - v[4*r+1];
                o.z = p.z - v[4*r+2]; o.w = p.w - v[4*r+3];
            }
            // index = half*1024 + r*128 + ... ; negative iff half==1 && r>=4
            const float s = (half == 1 && r >= 4) ? -S : S;
            o.x *= s; o.y *= s; o.z *= s; o.w *= s;
            dst[r * 32 + lane] = o;
        }
    }
}

extern "C" void kernel_launch(void* const* d_in, const int* in_sizes, int n_in,
                              void* d_out, int out_size) {
    const float* x = (const float*)d_in[0];
    float* out = (float*)d_out;
    const int rows   = in_sizes[0] / 2048;     // 16384
    const int blocks = (rows + 3) / 4;         // 4 rows per 256-thread block
    fwht_sign_kernel2<<<blocks, 256>>>(x, out, rows);
}

// round 7
// speedup vs baseline: 1.0063x; 1.0063x over previous
#include <cuda_runtime.h>

// FWHT (11 stages, N=2048) + sign flip on last quarter, batch 16384.
// TWO warps per row, 32 fp32/thread. Per half-row (fixed bit10):
//   bits 0,1  -> register-local (inside float4)
//   bits 2..6 -> warp shuffles (5 stages x 32 values)
//   bits 7,8,9-> register-local across r (3 bits)
//   bit 10    -> one shared-memory half-exchange between the warp pair
// Scale (1/sqrt2)^11 = 2^-5.5 folded into store; sign<0 iff i>=1536 <=> (bit10 & bit9).

__global__ void __launch_bounds__(256)
fwht_sign_kernel2(const float* __restrict__ in, float* __restrict__ out, int rows) {
    __shared__ float sbuf[4][2048];          // 4 rows per 256-thread block, 32 KB

    const int warp     = threadIdx.x >> 5;   // 0..7
    const int lane     = threadIdx.x & 31;
    const int rowLocal = warp >> 1;          // 0..3
    const int half     = warp & 1;           // bit 10 of the global index
    const int row      = blockIdx.x * 4 + rowLocal;
    const bool active  = (row < rows);

    float v[32];

    if (active) {
        const float4* __restrict__ src =
            reinterpret_cast<const float4*>(in) + (size_t)row * 512 + half * 256;

        // Coalesced load: 8 x float4, each instr covers 512 contiguous bytes.
        #pragma unroll
        for (int r = 0; r < 8; r++) {
            float4 f = src[r * 32 + lane];
            v[4*r+0] = f.x; v[4*r+1] = f.y; v[4*r+2] = f.z; v[4*r+3] = f.w;
        }

        // Stages bit0, bit1 (inside the float4).
        #pragma unroll
        for (int r = 0; r < 8; r++) {
            float a0 = v[4*r+0], a1 = v[4*r+1], a2 = v[4*r+2], a3 = v[4*r+3];
            float b0 = a0 + a1, b1 = a0 - a1, b2 = a2 + a3, b3 = a2 - a3;
            v[4*r+0] = b0 + b2;
            v[4*r+1] = b1 + b3;
            v[4*r+2] = b0 - b2;
            v[4*r+3] = b1 - b3;
        }

        // Stages bits 2..6 (lane bits) via warp shuffles.
        #pragma unroll
        for (int h = 1; h <= 16; h <<= 1) {
            const bool upper = (lane & h) != 0;
            #pragma unroll
            for (int k = 0; k < 32; k++) {
                float o = __shfl_xor_sync(0xffffffffu, v[k], h);
                v[k] = upper ? (o - v[k]) : (v[k] + o);
            }
        }

        // Stages bits 7,8,9 (r bits), register-local.
        #pragma unroll
        for (int rh = 1; rh <= 4; rh <<= 1) {
            #pragma unroll
            for (int r = 0; r < 8; r++) {
                if (r & rh) continue;
                #pragma unroll
                for (int c = 0; c < 4; c++) {
                    float a = v[4*r+c];
                    float b = v[4*(r|rh)+c];
                    v[4*r+c]      = a + b;
                    v[4*(r|rh)+c] = a - b;
                }
            }
        }

        // Publish own half to shared memory (conflict-free STS.128).
        float4* sb = reinterpret_cast<float4*>(sbuf[rowLocal]);
        #pragma unroll
        for (int r = 0; r < 8; r++) {
            float4 f;
            f.x = v[4*r+0]; f.y = v[4*r+1]; f.z = v[4*r+2]; f.w = v[4*r+3];
            sb[half * 256 + r * 32 + lane] = f;
        }
    }

    __syncthreads();

    if (active) {
        const float4* sb = reinterpret_cast<const float4*>(sbuf[rowLocal]);
        float4* __restrict__ dst =
            reinterpret_cast<float4*>(out) + (size_t)row * 512 + half * 256;

        const float S = 0.022097086912079612f;   // (1/sqrt(2))^11

        // Stage bit10 from partner half + scale/sign + coalesced store.
        #pragma unroll
        for (int r = 0; r < 8; r++) {
            float4 p = sb[(half ^ 1) * 256 + r * 32 + lane];
            float4 o;
            if (half == 0) {           // out = a + b
                o.x = v[4*r+0] + p.x; o.y = v[4*r+1] + p.y;
                o.z = v[4*r+2] + p.z; o.w = v[4*r+3] + p.w;
            } else {                   // out = a - b  (a = partner's low half)
                o.x = p.x - v[4*r+0]; o.y = p.y - v[4*r+1];
                o.z = p.z - v[4*r+2]; o.w = p.w - v[4*r+3];
            }
            // index = half*1024 + r*128 + ... ; negative iff half==1 && r>=4
            const float s = (half == 1 && r >= 4) ? -S : S;
            o.x *= s; o.y *= s; o.z *= s; o.w *= s;
            dst[r * 32 + lane] = o;
        }
    }
}

extern "C" void kernel_launch(void* const* d_in, const int* in_sizes, int n_in,
                              void* d_out, int out_size) {
    const float* x = (const float*)d_in[0];
    float* out = (float*)d_out;
    const int rows   = in_sizes[0] / 2048;     // 16384
    const int blocks = (rows + 3) / 4;         // 4 rows per 256-thread block
    fwht_sign_kernel2<<<blocks, 256>>>(x, out, rows);
}